// round 10
// baseline (speedup 1.0000x reference)
#include <cuda_runtime.h>
#include <math.h>

#define Bq 4
#define Nq 512
#define DIN 128
#define F 64
#define NN (Nq*Nq)
#define ALPHA 0.2f
#define MSPLIT 4
#define MCHUNK (Nq/MSPLIT)     // 128
#define KS 8
#define KC (DIN/KS)            // 16
#define NR (Bq*Nq)             // 2048 rows

// zeroed region: [s1 | t | sum | acc | ctrA | ctrB]
#define ZOFF_S1   0
#define ZOFF_T    (NR)
#define ZOFF_SUM  (2*NR)
#define ZOFF_ACC  (3*NR)
#define ZOFF_CTRA (3*NR + NR*F)        // 128 ints
#define ZOFF_CTRB (ZOFF_CTRA + 128)    // 256 ints
#define ZTOTAL    (ZOFF_CTRB + 256)

__device__ float g_zero[ZTOTAL];
__device__ float g_hpart[(long)KS*NR*F];   // 4MB k-partials (not zeroed)
__device__ float g_h[NR*F];                // combined h (not zeroed)

// ---------------------------------------------------------------------------
// Kernel A: split-k8 vec4 GEMM partials + atomic s1/t + last-block h combine.
// thread=(f4,row). 16 rows x 16 k per block. Grid 1024 = 8192 warps.
// ---------------------------------------------------------------------------
__global__ __launch_bounds__(256) void gat_h_kernel(
    const float* __restrict__ x, const float* __restrict__ W,
    const float* __restrict__ bias, const float* __restrict__ a)
{
    __shared__ __align__(16) float xs[16*KC];   // 1KB
    __shared__ int lastA;

    int bid  = blockIdx.x;
    int kc   = bid & 7;
    int rb   = bid >> 3;
    int row0 = rb * 16;
    int k0   = kc * KC;

    int tid   = threadIdx.x;
    int f4    = tid & 15;
    int rslot = tid >> 4;
    int row   = row0 + rslot;

    if (tid < 64) {
        int r = tid >> 2, c = tid & 3;
        ((float4*)xs)[tid] = *(const float4*)(x + (long)(row0 + r)*DIN + k0 + c*4);
    }
    __syncthreads();

    const float4* W4 = (const float4*)(W + (long)k0*F);   // [k][16 quads]
    float4 acc = (kc == 0) ? ((const float4*)bias)[f4]
                           : make_float4(0.f, 0.f, 0.f, 0.f);
    const float* xr = xs + rslot*KC;

    #pragma unroll
    for (int k = 0; k < KC; ++k) {
        float4 w  = W4[k*16 + f4];
        float  xk = xr[k];
        acc.x += xk*w.x; acc.y += xk*w.y; acc.z += xk*w.z; acc.w += xk*w.w;
    }

    ((float4*)g_hpart)[((long)kc*NR + row)*16 + f4] = acc;

    float4 a1 = ((const float4*)a)[f4];
    float4 a2 = ((const float4*)a)[16 + f4];
    float s1 = acc.x*a1.x + acc.y*a1.y + acc.z*a1.z + acc.w*a1.w;
    float t  = acc.x*a2.x + acc.y*a2.y + acc.z*a2.z + acc.w*a2.w;
    #pragma unroll
    for (int o = 8; o; o >>= 1) {        // reduce within 16-lane row group
        s1 += __shfl_xor_sync(0xffffffffu, s1, o);
        t  += __shfl_xor_sync(0xffffffffu, t,  o);
    }
    if (f4 == 0) {
        atomicAdd(g_zero + ZOFF_S1 + row, s1);
        atomicAdd(g_zero + ZOFF_T  + row, t);
    }

    // ---- last of 8 kc-blocks combines h partials ----
    __threadfence();
    if (tid == 0) {
        int* ctr = (int*)(g_zero + ZOFF_CTRA);
        lastA = (atomicAdd(ctr + rb, 1) == KS-1);
    }
    __syncthreads();
    if (lastA) {
        const float4* hp = (const float4*)g_hpart;
        long idx = (long)row*16 + f4;          // one float4 per thread
        float4 s = __ldcg(hp + idx);           // kc = 0
        #pragma unroll
        for (int kc2 = 1; kc2 < KS; ++kc2) {
            float4 v = __ldcg(hp + (long)kc2*NR*16 + idx);
            s.x += v.x; s.y += v.y; s.z += v.z; s.w += v.w;
        }
        ((float4*)g_h)[idx] = s;
    }
}

// ---------------------------------------------------------------------------
// Kernel B: 8 rows x 128-m chunk per block, grid 1024. Fused logits+exp+AV,
// atomic accumulate, last of 4 ms-blocks normalizes + elu + writes out.
// ---------------------------------------------------------------------------
__global__ __launch_bounds__(256) void gat_attn_kernel(
    const int* __restrict__ adj, float* __restrict__ out)
{
    __shared__ float s1s[Nq];
    __shared__ float ts [Nq];
    __shared__ __align__(16) float buf[4096];   // probs[8][128] (4KB) then red (16KB)
    __shared__ int lastB;
    float (*probs)[MCHUNK] = (float(*)[MCHUNK])buf;

    int tid  = threadIdx.x;
    int lane = tid & 31;
    int wid  = tid >> 5;                 // 0..7
    int bid  = blockIdx.x;
    int ms   = bid & 3;
    int rb   = (bid >> 2) & 63;
    int b    = bid >> 8;
    int n0   = rb << 3;
    int m0   = ms * MCHUNK;

    const float* gs1 = g_zero + ZOFF_S1;
    const float* gt  = g_zero + ZOFF_T;
    for (int i = tid; i < Nq; i += 256) {
        s1s[i] = gs1[b*Nq + i];
        ts [i] = gt [b*Nq + i];
    }
    __syncthreads();

    // ---- phase 1: exp(leakyrelu(logits)) masked, + row sums (atomic) ----
    {
        int n  = n0 + wid;
        int ma = m0 + lane*4;
        const int4 av = *(const int4*)(adj + ((long)b*Nq + n)*Nq + ma);
        int avv[4] = {av.x, av.y, av.z, av.w};
        float4 p4;
        float* pp = (float*)&p4;
        float sum = 0.f;
        #pragma unroll
        for (int j = 0; j < 4; ++j) {
            int m  = ma + j;
            int q1 = 2*(n*Nq + m);
            int idx1 = (q1   < NN) ? (q1   >> 9) : ((q1   - NN) & (Nq-1));
            int idx2 = (q1+1 < NN) ? ((q1+1)>> 9) : ((q1+1 - NN) & (Nq-1));
            float e = s1s[idx1] + ts[idx2];
            e = (e > 0.0f) ? e : ALPHA*e;
            float p = (avv[j] > 0) ? __expf(e) : 0.0f;
            pp[j] = p; sum += p;
        }
        *(float4*)&probs[wid][lane*4] = p4;
        #pragma unroll
        for (int o = 16; o; o >>= 1) sum += __shfl_xor_sync(0xffffffffu, sum, o);
        if (lane == 0) atomicAdd(g_zero + ZOFF_SUM + b*Nq + n, sum);
    }
    __syncthreads();

    // ---- phase 2: partial AV. warp = 16 contiguous m, lane = f2 ----
    float2 acc[8];
    #pragma unroll
    for (int r = 0; r < 8; ++r) acc[r] = make_float2(0.f, 0.f);

    const float2* h2 = (const float2*)(g_h + (long)b*Nq*F);
    #pragma unroll
    for (int kcc = 0; kcc < 4; ++kcc) {
        int mloc = wid*16 + kcc*4;
        int mabs = m0 + mloc;
        float2 hv0 = h2[(mabs+0)*32 + lane];
        float2 hv1 = h2[(mabs+1)*32 + lane];
        float2 hv2 = h2[(mabs+2)*32 + lane];
        float2 hv3 = h2[(mabs+3)*32 + lane];
        #pragma unroll
        for (int r = 0; r < 8; ++r) {
            float4 p = *(const float4*)&probs[r][mloc];
            acc[r].x += p.x*hv0.x + p.y*hv1.x + p.z*hv2.x + p.w*hv3.x;
            acc[r].y += p.x*hv0.y + p.y*hv1.y + p.z*hv2.y + p.w*hv3.y;
        }
    }
    __syncthreads();                      // probs dead; buf becomes red (16KB)

    float2* red = (float2*)buf;           // [8 g][8 r][32 f2]
    #pragma unroll
    for (int r = 0; r < 8; ++r)
        red[(wid*8 + r)*32 + lane] = acc[r];
    __syncthreads();

    {
        int r = wid;
        float2 o = make_float2(0.f, 0.f);
        #pragma unroll
        for (int g = 0; g < 8; ++g) {
            float2 v = red[(g*8 + r)*32 + lane];
            o.x += v.x; o.y += v.y;
        }
        float* adst = g_zero + ZOFF_ACC + ((long)b*Nq + n0 + r)*F + lane*2;
        atomicAdd(adst + 0, o.x);
        atomicAdd(adst + 1, o.y);
    }

    // ---- last of 4 ms-blocks finalizes these 8 rows ----
    __threadfence();
    if (tid == 0) {
        int* ctr = (int*)(g_zero + ZOFF_CTRB);
        lastB = (atomicAdd(ctr + b*64 + rb, 1) == MSPLIT-1);
    }
    __syncthreads();
    if (lastB) {
        int r  = tid >> 5;                  // row 0..7
        int f2 = tid & 31;                  // feature pair
        long rowg = (long)b*Nq + n0 + r;
        float inv = 1.0f / __ldcg(g_zero + ZOFF_SUM + rowg);
        float2 v  = __ldcg((const float2*)(g_zero + ZOFF_ACC + rowg*F) + f2);
        v.x *= inv; v.y *= inv;
        v.x = (v.x > 0.0f) ? v.x : expm1f(v.x);
        v.y = (v.y > 0.0f) ? v.y : expm1f(v.y);
        ((float2*)out)[rowg*32 + f2] = v;
    }
}

// ---------------------------------------------------------------------------
extern "C" void kernel_launch(void* const* d_in, const int* in_sizes, int n_in,
                              void* d_out, int out_size)
{
    const float* x    = (const float*)d_in[0];
    const int*   adj  = (const int*)  d_in[1];
    const float* W    = (const float*)d_in[2];
    const float* bias = (const float*)d_in[3];
    const float* a    = (const float*)d_in[4];
    float* out = (float*)d_out;

    void* zptr = nullptr;
    cudaGetSymbolAddress(&zptr, g_zero);
    cudaMemsetAsync(zptr, 0, ZTOTAL * sizeof(float));

    gat_h_kernel<<<(NR/16)*KS, 256>>>(x, W, bias, a);
    gat_attn_kernel<<<Bq*64*MSPLIT, 256>>>(adj, out);
}

// round 11
// speedup vs baseline: 1.2056x; 1.2056x over previous
#include <cuda_runtime.h>
#include <math.h>

#define Bq 4
#define Nq 512
#define DIN 128
#define F 64
#define NN (Nq*Nq)
#define ALPHA 0.2f
#define MSPLIT 4
#define MCHUNK (Nq/MSPLIT)     // 128
#define NR (Bq*Nq)             // 2048 rows
#define AROWS 4                // rows per A-block

// scratch (plain stores only — nothing needs zeroing)
__device__ float g_h [NR*F];
__device__ float g_s1[NR];
__device__ float g_t [NR];
__device__ float g_part[MSPLIT*NR*F];      // AV partials
__device__ float g_psum[MSPLIT*NR];        // row-sum partials

// ---------------------------------------------------------------------------
// Kernel A: fused h = x@W+b, s1, t. One kernel, in-block k-split.
// 1024 thr: thread = (f4 0..15, row 0..3, kc 0..15), KC=8 k per thread.
// Partials reduced in smem; 64 threads finalize. Grid 512.
// ---------------------------------------------------------------------------
__global__ __launch_bounds__(1024) void gat_h_kernel(
    const float* __restrict__ x, const float* __restrict__ W,
    const float* __restrict__ bias, const float* __restrict__ a)
{
    __shared__ __align__(16) float4 part[16*AROWS*16];  // [kc][row][f4] 16KB
    __shared__ __align__(16) float xs[AROWS*DIN];       // 2KB

    int tid  = threadIdx.x;
    int f4   = tid & 15;
    int row  = (tid >> 4) & 3;
    int kc   = tid >> 6;                 // 0..15
    int row0 = blockIdx.x * AROWS;

    if (tid < AROWS*DIN/4)               // 128 threads stage x
        ((float4*)xs)[tid] = ((const float4*)(x + (long)row0*DIN))[tid];
    __syncthreads();

    const float4* W4 = (const float4*)W;           // [k][16 quads]
    const float*  xr = xs + row*DIN + kc*8;
    float4 acc = make_float4(0.f, 0.f, 0.f, 0.f);
    #pragma unroll
    for (int k = 0; k < 8; ++k) {
        float4 w  = W4[(kc*8 + k)*16 + f4];
        float  xk = xr[k];
        acc.x += xk*w.x; acc.y += xk*w.y; acc.z += xk*w.z; acc.w += xk*w.w;
    }
    part[kc*(AROWS*16) + row*16 + f4] = acc;
    __syncthreads();

    if (tid < AROWS*16) {                // 64 threads finalize
        int rr = tid >> 4;
        int ff = tid & 15;
        float4 s = ((const float4*)bias)[ff];
        #pragma unroll
        for (int c = 0; c < 16; ++c) {
            float4 v = part[c*(AROWS*16) + tid];
            s.x += v.x; s.y += v.y; s.z += v.z; s.w += v.w;
        }
        ((float4*)g_h)[(long)(row0 + rr)*16 + ff] = s;

        float4 a1 = ((const float4*)a)[ff];
        float4 a2 = ((const float4*)a)[16 + ff];
        float s1 = s.x*a1.x + s.y*a1.y + s.z*a1.z + s.w*a1.w;
        float t  = s.x*a2.x + s.y*a2.y + s.z*a2.z + s.w*a2.w;
        #pragma unroll
        for (int o = 8; o; o >>= 1) {    // 16-lane row group
            s1 += __shfl_xor_sync(0xffffffffu, s1, o);
            t  += __shfl_xor_sync(0xffffffffu, t,  o);
        }
        if (ff == 0) { g_s1[row0 + rr] = s1; g_t[row0 + rr] = t; }
    }
}

// ---------------------------------------------------------------------------
// Kernel B: 8 rows x 128-m chunk per block. 256 threads, grid 1024.
// Fused: masked exp(leakyrelu(logits)) + row sums + partial AV. Plain stores.
// ---------------------------------------------------------------------------
__global__ __launch_bounds__(256) void gat_attn_kernel(const int* __restrict__ adj)
{
    __shared__ float s1s[Nq];
    __shared__ float ts [Nq];
    __shared__ __align__(16) float buf[4096];   // probs[8][128] (4KB) then red (16KB)
    float (*probs)[MCHUNK] = (float(*)[MCHUNK])buf;

    int tid  = threadIdx.x;
    int lane = tid & 31;
    int wid  = tid >> 5;                 // 0..7
    int bid  = blockIdx.x;
    int ms   = bid & 3;
    int rb   = (bid >> 2) & 63;
    int b    = bid >> 8;
    int n0   = rb << 3;
    int m0   = ms * MCHUNK;

    for (int i = tid; i < Nq; i += 256) {
        s1s[i] = g_s1[b*Nq + i];
        ts [i] = g_t [b*Nq + i];
    }
    __syncthreads();

    // ---- phase 1: exp(leakyrelu(logits)) masked, + row partial sums ----
    {
        int n  = n0 + wid;
        int ma = m0 + lane*4;
        const int4 av = *(const int4*)(adj + ((long)b*Nq + n)*Nq + ma);
        int avv[4] = {av.x, av.y, av.z, av.w};
        float4 p4;
        float* pp = (float*)&p4;
        float sum = 0.f;
        #pragma unroll
        for (int j = 0; j < 4; ++j) {
            int m  = ma + j;
            int q1 = 2*(n*Nq + m);
            int idx1 = (q1   < NN) ? (q1   >> 9) : ((q1   - NN) & (Nq-1));
            int idx2 = (q1+1 < NN) ? ((q1+1)>> 9) : ((q1+1 - NN) & (Nq-1));
            float e = s1s[idx1] + ts[idx2];
            e = (e > 0.0f) ? e : ALPHA*e;
            float p = (avv[j] > 0) ? __expf(e) : 0.0f;
            pp[j] = p; sum += p;
        }
        *(float4*)&probs[wid][lane*4] = p4;
        #pragma unroll
        for (int o = 16; o; o >>= 1) sum += __shfl_xor_sync(0xffffffffu, sum, o);
        if (lane == 0) g_psum[(ms*Bq + b)*Nq + n] = sum;
    }
    __syncthreads();

    // ---- phase 2: partial AV. warp = 16 contiguous m, lane = f2 ----
    float2 acc[8];
    #pragma unroll
    for (int r = 0; r < 8; ++r) acc[r] = make_float2(0.f, 0.f);

    const float2* h2 = (const float2*)(g_h + (long)b*Nq*F);
    #pragma unroll
    for (int kcc = 0; kcc < 4; ++kcc) {
        int mloc = wid*16 + kcc*4;
        int mabs = m0 + mloc;
        float2 hv0 = h2[(mabs+0)*32 + lane];
        float2 hv1 = h2[(mabs+1)*32 + lane];
        float2 hv2 = h2[(mabs+2)*32 + lane];
        float2 hv3 = h2[(mabs+3)*32 + lane];
        #pragma unroll
        for (int r = 0; r < 8; ++r) {
            float4 p = *(const float4*)&probs[r][mloc];
            acc[r].x += p.x*hv0.x + p.y*hv1.x + p.z*hv2.x + p.w*hv3.x;
            acc[r].y += p.x*hv0.y + p.y*hv1.y + p.z*hv2.y + p.w*hv3.y;
        }
    }
    __syncthreads();                      // probs dead; buf becomes red (16KB)

    float2* red = (float2*)buf;           // [8 g][8 r][32 f2]
    #pragma unroll
    for (int r = 0; r < 8; ++r)
        red[(wid*8 + r)*32 + lane] = acc[r];
    __syncthreads();

    {
        int r = wid;
        float2 o = make_float2(0.f, 0.f);
        #pragma unroll
        for (int g = 0; g < 8; ++g) {
            float2 v = red[(g*8 + r)*32 + lane];
            o.x += v.x; o.y += v.y;
        }
        ((float2*)g_part)[((long)(ms*Bq + b)*Nq + n0 + r)*32 + lane] = o;
    }
}

// ---------------------------------------------------------------------------
// Kernel C: combine + normalize + elu. Thread = one output element,
// fully coalesced. Grid 512 x 256 thr = 4096 warps.
// ---------------------------------------------------------------------------
__global__ __launch_bounds__(256) void gat_combine_kernel(float* __restrict__ out)
{
    int gid = blockIdx.x*256 + threadIdx.x;   // 0..131071
    int row = gid >> 6;                       // F=64

    float acc = 0.f, s = 0.f;
    #pragma unroll
    for (int ms = 0; ms < MSPLIT; ++ms) {
        acc += g_part[(long)ms*NR*F + gid];
        s   += g_psum[ms*NR + row];
    }
    float v = acc / s;
    out[gid] = (v > 0.0f) ? v : expm1f(v);
}

// ---------------------------------------------------------------------------
extern "C" void kernel_launch(void* const* d_in, const int* in_sizes, int n_in,
                              void* d_out, int out_size)
{
    const float* x    = (const float*)d_in[0];
    const int*   adj  = (const int*)  d_in[1];
    const float* W    = (const float*)d_in[2];
    const float* bias = (const float*)d_in[3];
    const float* a    = (const float*)d_in[4];
    float* out = (float*)d_out;

    gat_h_kernel<<<NR/AROWS, 1024>>>(x, W, bias, a);
    gat_attn_kernel<<<Bq*64*MSPLIT, 256>>>(adj);
    gat_combine_kernel<<<(NR*F)/256, 256>>>(out);
}